// round 12
// baseline (speedup 1.0000x reference)
#include <cuda_runtime.h>
#include <cuda_bf16.h>

#define N_NODES    1000000
#define NUM_GRAPHS 1024

// ---- binning geometry -------------------------------------------------------
#define BIN_SHIFT  11                       // 2048 nodes per bin
#define BIN_NODES  2048
#define NBINS      512                      // allocated (power of 2 for scan)
#define NBINS_USED 489                      // ceil(1e6 / 2048)
#define BIN_CAP    73728u                   // mean 65.4K + ~32 sigma
#define EPB        8192                     // edges per block, pass 1
#define P1_THREADS 256
#define P2_THREADS 256

// Scratch — zero-initialized at module load. Zero-invariant: every
// kernel_launch call starts AND ends with d_agg/d_gsum/d_gcnt/d_cursor zeroed
// (each consumer restores what it consumed), so replays are deterministic.
__device__ float d_agg[N_NODES];
__device__ float d_gsum[NUM_GRAPHS];
__device__ float d_gcnt[NUM_GRAPHS];
__device__ unsigned int d_cursor[NBINS];
__device__ unsigned int d_entries[(size_t)NBINS * BIN_CAP];   // ~151 MB

// ---------------------------------------------------------------------------
// Per-block index-dtype detection (JAX x64-off downcasts int64->int32; an
// int32 pair reinterpreted as u64 is >= 2^32 w.p. ~1, true int64 idx < 1e6).
// All blocks read the SAME 8 words -> all agree.
// ---------------------------------------------------------------------------
__device__ __forceinline__ int detect_is64(const void* edges) {
    const unsigned long long* p = (const unsigned long long*)edges;
    int is64 = 1;
    #pragma unroll
    for (int k = 0; k < 8; k++)
        if (__ldg(&p[k]) >= (1ull << 32)) is64 = 0;
    return is64;
}

// ---------------------------------------------------------------------------
// PASS 1: block counting-sort of edges into dst-range bins.
// Entry = (src << 11) | (dst & 2047)  — 4 bytes, dst-high = bin id.
// Flush is warp-cooperative per-bin runs -> coalesced global writes.
// ---------------------------------------------------------------------------
__global__ void __launch_bounds__(P1_THREADS) bin_kernel(
        const void* __restrict__ edge_ptr,
        const float* __restrict__ x,
        long long n_edges) {
    __shared__ int          s_is64;
    __shared__ unsigned int s_cnt[NBINS];    // per-block per-bin counts
    __shared__ unsigned int s_off[NBINS];    // phase-B insertion cursors
    __shared__ unsigned int s_start[NBINS];  // exclusive prefix of counts
    __shared__ unsigned int s_gbase[NBINS];  // reserved global base per bin
    __shared__ unsigned int s_entries[EPB];  // 32KB staging
    __shared__ unsigned int s_scanw[P1_THREADS / 32];

    const int tid  = threadIdx.x;
    const int lane = tid & 31;
    const int wid  = tid >> 5;

    if (tid == 0) s_is64 = detect_is64(edge_ptr);
    for (int i = tid; i < NBINS; i += P1_THREADS) { s_cnt[i] = 0; s_off[i] = 0; }
    __syncthreads();
    const int is64 = s_is64;

    const long long e0   = (long long)blockIdx.x * EPB;
    const int       nblk = (int)((n_edges - e0) < EPB ? (n_edges - e0) : EPB);

    // ---- Phase A: count dst bins (coalesced dst reads) ----
    for (int i = tid; i < nblk; i += P1_THREADS) {
        long long e = e0 + i;
        int dst = is64 ? (int)__ldg(&((const long long*)edge_ptr)[n_edges + e])
                       : __ldg(&((const int*)edge_ptr)[n_edges + e]);
        atomicAdd(&s_cnt[dst >> BIN_SHIFT], 1u);
    }
    __syncthreads();

    // ---- block exclusive scan over 512 counts (2 bins / thread) ----
    unsigned int c0 = s_cnt[2 * tid];
    unsigned int c1 = s_cnt[2 * tid + 1];
    unsigned int v  = c0 + c1;              // thread total
    unsigned int inc = v;
    #pragma unroll
    for (int off = 1; off < 32; off <<= 1) {
        unsigned int u = __shfl_up_sync(0xffffffffu, inc, off);
        if (lane >= off) inc += u;
    }
    if (lane == 31) s_scanw[wid] = inc;
    __syncthreads();
    if (wid == 0) {
        unsigned int w = (lane < P1_THREADS / 32) ? s_scanw[lane] : 0u;
        #pragma unroll
        for (int off = 1; off < 32; off <<= 1) {
            unsigned int u = __shfl_up_sync(0xffffffffu, w, off);
            if (lane >= off) w += u;
        }
        if (lane < P1_THREADS / 32) s_scanw[lane] = w;
    }
    __syncthreads();
    unsigned int excl = inc - v + (wid ? s_scanw[wid - 1] : 0u);
    s_start[2 * tid]     = excl;
    s_start[2 * tid + 1] = excl + c0;
    // reserve contiguous global runs
    if (c0) s_gbase[2 * tid]     = atomicAdd(&d_cursor[2 * tid],     c0);
    if (c1) s_gbase[2 * tid + 1] = atomicAdd(&d_cursor[2 * tid + 1], c1);
    __syncthreads();

    // ---- Phase B: place packed entries into smem (bin-sorted) ----
    for (int i = tid; i < nblk; i += P1_THREADS) {
        long long e = e0 + i;
        int src, dst;
        if (is64) {
            src = (int)__ldg(&((const long long*)edge_ptr)[e]);
            dst = (int)__ldg(&((const long long*)edge_ptr)[n_edges + e]);
        } else {
            src = __ldg(&((const int*)edge_ptr)[e]);
            dst = __ldg(&((const int*)edge_ptr)[n_edges + e]);
        }
        int b = dst >> BIN_SHIFT;
        unsigned int p = atomicAdd(&s_off[b], 1u);
        s_entries[s_start[b] + p] =
            ((unsigned int)src << BIN_SHIFT) | (unsigned int)(dst & (BIN_NODES - 1));
    }
    __syncthreads();

    // ---- Phase C: coalesced flush of per-bin runs ----
    const int nwarp = P1_THREADS / 32;
    for (int b = wid; b < NBINS; b += nwarp) {
        unsigned int n = s_cnt[b];
        if (!n) continue;
        unsigned int st = s_start[b];
        unsigned int gb = s_gbase[b];
        size_t gbase = (size_t)b * BIN_CAP;
        for (unsigned int i = lane; i < n; i += 32) {
            unsigned int ent = s_entries[st + i];
            unsigned int gp  = gb + i;
            if (gp < BIN_CAP) {
                d_entries[gbase + gp] = ent;
            } else {
                // capacity overflow (never for uniform dst): apply directly
                int dl  = (int)(ent & (BIN_NODES - 1));
                int src = (int)(ent >> BIN_SHIFT);
                atomicAdd(&d_agg[(b << BIN_SHIFT) + dl], __ldg(&x[src]));
            }
        }
    }
}

// ---------------------------------------------------------------------------
// PASS 2: one block per bin. Stream entries (coalesced), gather x[src]
// (the single remaining random op), accumulate in an 8KB smem tile, flush
// coalesced. Resets d_cursor (zero-invariant).
// ---------------------------------------------------------------------------
__global__ void __launch_bounds__(P2_THREADS) accum_kernel(
        const float* __restrict__ x) {
    __shared__ float s_agg[BIN_NODES];        // 8KB
    const int b   = blockIdx.x;
    const int tid = threadIdx.x;

    for (int j = tid; j < BIN_NODES; j += P2_THREADS) s_agg[j] = 0.0f;
    __syncthreads();

    unsigned int n = d_cursor[b];
    if (n > BIN_CAP) n = BIN_CAP;
    const size_t base = (size_t)b * BIN_CAP;

    unsigned int i = tid;
    for (; i + 3u * P2_THREADS < n; i += 4u * P2_THREADS) {   // MLP=4
        unsigned int e0 = __ldg(&d_entries[base + i]);
        unsigned int e1 = __ldg(&d_entries[base + i +     P2_THREADS]);
        unsigned int e2 = __ldg(&d_entries[base + i + 2u * P2_THREADS]);
        unsigned int e3 = __ldg(&d_entries[base + i + 3u * P2_THREADS]);
        float v0 = __ldg(&x[e0 >> BIN_SHIFT]);
        float v1 = __ldg(&x[e1 >> BIN_SHIFT]);
        float v2 = __ldg(&x[e2 >> BIN_SHIFT]);
        float v3 = __ldg(&x[e3 >> BIN_SHIFT]);
        atomicAdd(&s_agg[e0 & (BIN_NODES - 1)], v0);
        atomicAdd(&s_agg[e1 & (BIN_NODES - 1)], v1);
        atomicAdd(&s_agg[e2 & (BIN_NODES - 1)], v2);
        atomicAdd(&s_agg[e3 & (BIN_NODES - 1)], v3);
    }
    for (; i < n; i += P2_THREADS) {
        unsigned int e = __ldg(&d_entries[base + i]);
        atomicAdd(&s_agg[e & (BIN_NODES - 1)], __ldg(&x[e >> BIN_SHIFT]));
    }
    __syncthreads();

    const int node0 = b << BIN_SHIFT;
    for (int j = tid; j < BIN_NODES; j += P2_THREADS) {
        int idx = node0 + j;
        if (idx < N_NODES) d_agg[idx] += s_agg[j];  // += keeps overflow REDs
    }
    if (tid == 0) d_cursor[b] = 0;                  // restore zero-invariant
}

// ---------------------------------------------------------------------------
// ReLU + segmented pool with warp-aggregated atomics (proven in R8-R10).
// Each thread: 8 contiguous nodes; warp-uniform fast path -> 2 REDs/warp.
// Also zeroes consumed d_agg (zero-invariant).
// ---------------------------------------------------------------------------
#define NODES_PER_THREAD 8
__global__ void __launch_bounds__(256) pool_kernel(
        const void* __restrict__ batch_ptr,
        const void* __restrict__ edge_ptr) {
    __shared__ int s_is64;
    if (threadIdx.x == 0) s_is64 = detect_is64(edge_ptr);
    __syncthreads();
    const int is64 = s_is64;

    long long t    = (long long)blockIdx.x * blockDim.x + threadIdx.x;
    long long base = t * NODES_PER_THREAD;
    const bool valid = (base < N_NODES);

    int   g[NODES_PER_THREAD];
    float h[NODES_PER_THREAD];
    float s_loc = 0.0f;

    if (valid) {
        #pragma unroll
        for (int j = 0; j < NODES_PER_THREAD / 4; j++) {
            float4 a = *(const float4*)&d_agg[base + 4 * j];
            h[4*j] = a.x; h[4*j+1] = a.y; h[4*j+2] = a.z; h[4*j+3] = a.w;
        }
        #pragma unroll
        for (int j = 0; j < NODES_PER_THREAD / 4; j++)
            *(float4*)&d_agg[base + 4 * j] = make_float4(0.f, 0.f, 0.f, 0.f);

        if (is64) {
            const longlong2* bp = (const longlong2*)batch_ptr;
            #pragma unroll
            for (int j = 0; j < NODES_PER_THREAD / 2; j++) {
                longlong2 v = __ldg(&bp[(base >> 1) + j]);
                g[2*j] = (int)v.x; g[2*j+1] = (int)v.y;
            }
        } else {
            const int4* bp = (const int4*)batch_ptr;
            #pragma unroll
            for (int j = 0; j < NODES_PER_THREAD / 4; j++) {
                int4 v = __ldg(&bp[(base >> 2) + j]);
                g[4*j] = v.x; g[4*j+1] = v.y; g[4*j+2] = v.z; g[4*j+3] = v.w;
            }
        }
        #pragma unroll
        for (int k = 0; k < NODES_PER_THREAD; k++)
            s_loc += h[k] > 0.0f ? h[k] : 0.0f;
    } else {
        #pragma unroll
        for (int k = 0; k < NODES_PER_THREAD; k++) g[k] = -1;
    }

    int g_first = __shfl_sync(0xffffffffu, g[0], 0);
    bool lane_uniform = valid && (g[0] == g[NODES_PER_THREAD - 1]) &&
                        (g[0] == g_first);
    if (__all_sync(0xffffffffu, lane_uniform)) {
        float s_w = s_loc;
        #pragma unroll
        for (int off = 16; off > 0; off >>= 1)
            s_w += __shfl_xor_sync(0xffffffffu, s_w, off);
        if ((threadIdx.x & 31) == 0) {
            atomicAdd(&d_gsum[g_first], s_w);
            atomicAdd(&d_gcnt[g_first], 32.0f * NODES_PER_THREAD);
        }
        return;
    }

    if (!valid) return;
    int cur = g[0];
    float s = 0.0f, c = 0.0f;
    #pragma unroll
    for (int k = 0; k < NODES_PER_THREAD; k++) {
        float hv = h[k] > 0.0f ? h[k] : 0.0f;
        if (g[k] != cur) {
            atomicAdd(&d_gsum[cur], s);
            atomicAdd(&d_gcnt[cur], c);
            cur = g[k]; s = 0.0f; c = 0.0f;
        }
        s += hv; c += 1.0f;
    }
    atomicAdd(&d_gsum[cur], s);
    atomicAdd(&d_gcnt[cur], c);
}

// ---------------------------------------------------------------------------
// out[g] = (gsum/max(cnt,1)) * W + b; restores zero-invariant.
// ---------------------------------------------------------------------------
__global__ void out_kernel(const float* __restrict__ W,
                           const float* __restrict__ b,
                           float* __restrict__ out) {
    int g = blockIdx.x * blockDim.x + threadIdx.x;
    if (g < NUM_GRAPHS) {
        float sum = d_gsum[g];
        float cnt = fmaxf(d_gcnt[g], 1.0f);
        out[g] = (sum / cnt) * __ldg(&W[0]) + __ldg(&b[0]);
        d_gsum[g] = 0.0f;
        d_gcnt[g] = 0.0f;
    }
}

extern "C" void kernel_launch(void* const* d_in, const int* in_sizes, int n_in,
                              void* d_out, int out_size) {
    const float* x     = (const float*)d_in[0];
    const float* W     = (const float*)d_in[1];
    const float* b     = (const float*)d_in[2];
    const void*  edges = d_in[3];
    const void*  batch = d_in[4];
    long long n_edges  = (long long)in_sizes[3] / 2;   // [2, E] -> E

    int p1_blocks = (int)((n_edges + EPB - 1) / EPB);
    bin_kernel<<<p1_blocks, P1_THREADS>>>(edges, x, n_edges);

    accum_kernel<<<NBINS_USED, P2_THREADS>>>(x);

    long long pool_threads = (N_NODES + NODES_PER_THREAD - 1) / NODES_PER_THREAD;
    pool_kernel<<<(int)((pool_threads + 255) / 256), 256>>>(batch, edges);

    out_kernel<<<(NUM_GRAPHS + 255) / 256, 256>>>(W, b, (float*)d_out);
}

// round 13
// speedup vs baseline: 1.4806x; 1.4806x over previous
#include <cuda_runtime.h>
#include <cuda_bf16.h>

#define N_NODES    1000000
#define NUM_GRAPHS 1024

// Scratch — __device__ globals are ZERO-INITIALIZED at module load.
// Invariant: every kernel_launch call both starts AND ends with these zeroed
// (pool_kernel zeroes d_agg it consumed; out_kernel zeroes d_gsum/d_gcnt),
// so no init kernel is needed and graph replays are deterministic.
__device__ float d_agg[N_NODES];      // per-node aggregated sum
__device__ float d_gsum[NUM_GRAPHS];  // per-graph sum of relu(agg)
__device__ float d_gcnt[NUM_GRAPHS];  // per-graph node count

// ---------------------------------------------------------------------------
// Per-block index-dtype detection. JAX with x64 disabled silently downcasts
// int64->int32: an int32 pair reinterpreted as u64 is >= 2^32 unless the hi
// index is 0; sampling 8 fixed words makes misdetection probability ~0 and
// every block reads the SAME bytes, so all blocks agree.
// ---------------------------------------------------------------------------
__device__ __forceinline__ int detect_is64(const void* edges) {
    const unsigned long long* p = (const unsigned long long*)edges;
    int is64 = 1;
    #pragma unroll
    for (int k = 0; k < 8; k++)
        if (__ldg(&p[k]) >= (1ull << 32)) is64 = 0;
    return is64;
}

// ---------------------------------------------------------------------------
// Edge scatter: agg[dst[e]] += x[src[e]].  4 edges/thread — the measured
// optimum. This kernel runs at 92.7% L2 / 91.6% L1 utilization: 64M random
// lane-ops (32M gathers + 32M REDs) at ~1 L1tex wavefront each is the
// hardware floor (~236us). Block=512 halves per-block overhead vs 256.
// edge_index layout: [2, E] row-major -> src = [0,E), dst = [E, 2E).
// ---------------------------------------------------------------------------
#define EDGE_BLOCK 512
__global__ void __launch_bounds__(EDGE_BLOCK) edge_kernel(
        const void* __restrict__ edge_ptr,
        const float* __restrict__ x,
        long long n_edges) {
    __shared__ int s_is64;
    if (threadIdx.x == 0) s_is64 = detect_is64(edge_ptr);
    __syncthreads();
    const int is64 = s_is64;

    long long t    = (long long)blockIdx.x * EDGE_BLOCK + threadIdx.x;
    long long base = t * 4;
    if (base >= n_edges) return;

    int s[4], d[4];
    if (is64) {
        const longlong2* src2 = (const longlong2*)edge_ptr;          // 2 idx / 16B
        const longlong2* dst2 = src2 + (n_edges >> 1);
        longlong2 a = __ldg(&src2[base >> 1]);
        longlong2 b = __ldg(&src2[(base >> 1) + 1]);
        longlong2 c = __ldg(&dst2[base >> 1]);
        longlong2 e = __ldg(&dst2[(base >> 1) + 1]);
        s[0] = (int)a.x; s[1] = (int)a.y; s[2] = (int)b.x; s[3] = (int)b.y;
        d[0] = (int)c.x; d[1] = (int)c.y; d[2] = (int)e.x; d[3] = (int)e.y;
    } else {
        const int4* src4 = (const int4*)edge_ptr;                    // 4 idx / 16B
        const int4* dst4 = (const int4*)((const int*)edge_ptr + n_edges);
        int4 a = __ldg(&src4[base >> 2]);
        int4 c = __ldg(&dst4[base >> 2]);
        s[0] = a.x; s[1] = a.y; s[2] = a.z; s[3] = a.w;
        d[0] = c.x; d[1] = c.y; d[2] = c.z; d[3] = c.w;
    }

    #pragma unroll
    for (int k = 0; k < 4; k++) {
        if (base + k < n_edges) {
            float xv = __ldg(&x[s[k]]);
            atomicAdd(&d_agg[d[k]], xv);   // result unused -> RED.E.ADD.F32
        }
    }
}

// ---------------------------------------------------------------------------
// ReLU + segmented pool with WARP-AGGREGATED atomics (R10 proven shape).
// batch is SORTED. Each thread handles 8 contiguous nodes; a warp covers 256.
// Avg graph = ~977 nodes, so ~75% of warps lie entirely inside one graph:
// fast path warp-reduces the sum and lane 0 issues 2 atomics per warp
// (vs 64) -> ~10x fewer per-graph REDs, killing L2 atomic serialization.
// Each thread also zeroes its d_agg slots (restores the zero-invariant).
// ---------------------------------------------------------------------------
#define NODES_PER_THREAD 8
__global__ void __launch_bounds__(256) pool_kernel(
        const void* __restrict__ batch_ptr,
        const void* __restrict__ edge_ptr) {   // edge_ptr: dtype detect only
    __shared__ int s_is64;
    if (threadIdx.x == 0) s_is64 = detect_is64(edge_ptr);
    __syncthreads();
    const int is64 = s_is64;

    long long t    = (long long)blockIdx.x * blockDim.x + threadIdx.x;
    long long base = t * NODES_PER_THREAD;
    const bool valid = (base < N_NODES);   // N_NODES % 8 == 0 -> full 8 if valid

    int   g[NODES_PER_THREAD];
    float h[NODES_PER_THREAD];
    float s_loc = 0.0f;

    if (valid) {
        #pragma unroll
        for (int j = 0; j < NODES_PER_THREAD / 4; j++) {
            float4 a = *(const float4*)&d_agg[base + 4*j];
            h[4*j] = a.x; h[4*j+1] = a.y; h[4*j+2] = a.z; h[4*j+3] = a.w;
        }
        // restore zero-invariant for the next call / graph replay
        #pragma unroll
        for (int j = 0; j < NODES_PER_THREAD / 4; j++)
            *(float4*)&d_agg[base + 4*j] = make_float4(0.f, 0.f, 0.f, 0.f);

        if (is64) {
            const longlong2* bp = (const longlong2*)batch_ptr;
            #pragma unroll
            for (int j = 0; j < NODES_PER_THREAD / 2; j++) {
                longlong2 v = __ldg(&bp[(base >> 1) + j]);
                g[2*j] = (int)v.x; g[2*j+1] = (int)v.y;
            }
        } else {
            const int4* bp = (const int4*)batch_ptr;
            #pragma unroll
            for (int j = 0; j < NODES_PER_THREAD / 4; j++) {
                int4 v = __ldg(&bp[(base >> 2) + j]);
                g[4*j] = v.x; g[4*j+1] = v.y; g[4*j+2] = v.z; g[4*j+3] = v.w;
            }
        }
        #pragma unroll
        for (int k = 0; k < NODES_PER_THREAD; k++)
            s_loc += h[k] > 0.0f ? h[k] : 0.0f;
    } else {
        #pragma unroll
        for (int k = 0; k < NODES_PER_THREAD; k++) g[k] = -1;
    }

    // ---- warp-uniform fast path ----
    int g_first = __shfl_sync(0xffffffffu, g[0], 0);
    bool lane_uniform = valid && (g[0] == g[NODES_PER_THREAD - 1]) &&
                        (g[0] == g_first);
    if (__all_sync(0xffffffffu, lane_uniform)) {
        // whole warp (256 nodes) in one graph: butterfly-reduce sum
        float s_w = s_loc;
        #pragma unroll
        for (int off = 16; off > 0; off >>= 1)
            s_w += __shfl_xor_sync(0xffffffffu, s_w, off);
        if ((threadIdx.x & 31) == 0) {
            atomicAdd(&d_gsum[g_first], s_w);
            atomicAdd(&d_gcnt[g_first], 32.0f * NODES_PER_THREAD);
        }
        return;
    }

    // ---- slow path: per-thread segmented flush ----
    if (!valid) return;
    int cur = g[0];
    float s = 0.0f, c = 0.0f;
    #pragma unroll
    for (int k = 0; k < NODES_PER_THREAD; k++) {
        float hv = h[k] > 0.0f ? h[k] : 0.0f;
        if (g[k] != cur) {
            atomicAdd(&d_gsum[cur], s);
            atomicAdd(&d_gcnt[cur], c);
            cur = g[k]; s = 0.0f; c = 0.0f;
        }
        s += hv; c += 1.0f;
    }
    atomicAdd(&d_gsum[cur], s);
    atomicAdd(&d_gcnt[cur], c);
}

// ---------------------------------------------------------------------------
// out[g] = (gsum[g] / max(gcnt[g],1)) * W + b; then restore zero-invariant.
// Launch boundary provides all ordering — no fences. Single 1024-thread block.
// ---------------------------------------------------------------------------
__global__ void out_kernel(const float* __restrict__ W,
                           const float* __restrict__ b,
                           float* __restrict__ out) {
    int g = threadIdx.x;
    if (g < NUM_GRAPHS) {
        float sum = d_gsum[g];
        float cnt = fmaxf(d_gcnt[g], 1.0f);
        out[g] = (sum / cnt) * __ldg(&W[0]) + __ldg(&b[0]);
        d_gsum[g] = 0.0f;
        d_gcnt[g] = 0.0f;
    }
}

extern "C" void kernel_launch(void* const* d_in, const int* in_sizes, int n_in,
                              void* d_out, int out_size) {
    const float* x     = (const float*)d_in[0];
    const float* W     = (const float*)d_in[1];
    const float* b     = (const float*)d_in[2];
    const void*  edges = d_in[3];
    const void*  batch = d_in[4];
    long long n_edges  = (long long)in_sizes[3] / 2;   // [2, E] -> E

    long long edge_threads = (n_edges + 3) / 4;
    edge_kernel<<<(int)((edge_threads + EDGE_BLOCK - 1) / EDGE_BLOCK),
                  EDGE_BLOCK>>>(edges, x, n_edges);

    long long pool_threads = (N_NODES + NODES_PER_THREAD - 1) / NODES_PER_THREAD;
    pool_kernel<<<(int)((pool_threads + 255) / 256), 256>>>(batch, edges);

    out_kernel<<<1, 1024>>>(W, b, (float*)d_out);
}